// round 7
// baseline (speedup 1.0000x reference)
#include <cuda_runtime.h>
#include <math.h>

typedef unsigned long long ull;

#define NBATCH 2048
#define NPAIR 1024
#define FULLM 0xffffffffu

// ---------------- device scratch ----------------
__device__ __align__(16) ull g_wA[2700];                             // composed 5x5 weights (w,w) pairs
__device__ float g_b2[18];                                           // composed bias
__device__ __align__(16) ull g_w3[2916];                             // c3 weights (w,w)
__device__ __align__(16) ull g_w4[2916];                             // c4 weights (w,w)
__device__ __align__(16) ull g_pool1p[(size_t)NPAIR * 18 * 30 * 30]; // pool1, sample-pair interleaved
__device__ __align__(16) ull g_zp[(size_t)NPAIR * 18 * 28 * 28];     // conv3 out, interleaved
__device__ __align__(16) float g_feat[(size_t)NBATCH * 3042];        // flattened features

// ---------------- packed f32x2 helpers ----------------
__device__ __forceinline__ void ffma2(ull& d, ull a, ull b) {
    asm("fma.rn.f32x2 %0, %1, %2, %0;" : "+l"(d) : "l"(a), "l"(b));
}
__device__ __forceinline__ ull pk2(float lo, float hi) {
    ull r;
    asm("mov.b64 %0, {%1, %2};" : "=l"(r) : "f"(lo), "f"(hi));
    return r;
}
__device__ __forceinline__ float2 upk2(ull v) {
    float2 r;
    asm("mov.b64 {%0, %1}, %2;" : "=f"(r.x), "=f"(r.y) : "l"(v));
    return r;
}

// ---------------- compose conv1*conv2 -> one 5x5 conv ----------------
__global__ void k_compose(const float* __restrict__ c1w, const float* __restrict__ c1b,
                          const float* __restrict__ c2w, const float* __restrict__ c2b) {
    int idx = blockIdx.x * blockDim.x + threadIdx.x;
    if (idx < 2700) {
        int o = idx / 150;
        int ci = (idx / 25) % 6;
        int y = (idx % 25) / 5;
        int x = idx % 5;
        int ky_lo = y > 2 ? y - 2 : 0, ky_hi = y < 2 ? y : 2;
        int kx_lo = x > 2 ? x - 2 : 0, kx_hi = x < 2 ? x : 2;
        float s = 0.f;
        for (int m = 0; m < 18; m++)
            for (int ky = ky_lo; ky <= ky_hi; ky++)
                for (int kx = kx_lo; kx <= kx_hi; kx++)
                    s += c1w[((m * 6 + ci) * 3 + ky) * 3 + kx] *
                         c2w[((o * 18 + m) * 3 + (y - ky)) * 3 + (x - kx)];
        g_wA[idx] = pk2(s, s);
    } else if (idx < 2718) {
        int o = idx - 2700;
        float s = c2b[o];
        for (int m = 0; m < 18; m++) {
            float t = 0.f;
            for (int q = 0; q < 9; q++) t += c2w[(o * 18 + m) * 9 + q];
            s += c1b[m] * t;
        }
        g_b2[o] = s;
    }
}

__global__ void k_packw(const float* __restrict__ c3w, const float* __restrict__ c4w) {
    int idx = blockIdx.x * blockDim.x + threadIdx.x;
    if (idx < 2916) {
        float a = c3w[idx], b = c4w[idx];
        g_w3[idx] = pk2(a, a);
        g_w4[idx] = pk2(b, b);
    }
}

// ---------------- convA: composed 5x5 (6->18) + maxpool2 ----------------
// grid (30 rowpairs, 1024 pairs), 192 thr (6 warps = 6 oc-chunks of 3)
// lane L holds in-cols 2L,2L+1; halo via shfl.
__global__ __launch_bounds__(192, 5) void k_convA(const float* __restrict__ states) {
    __shared__ __align__(16) ull inP[6 * 6 * 64 + 8];
    const int tid = threadIdx.x;
    const int lane = tid & 31, warp = tid >> 5;
    const int r = blockIdx.x;
    const int pair = blockIdx.y;

    {
        const float4* s0 = (const float4*)(states) + (size_t)pair * 12288;
        // 6 ci x 6 rows x 16 float4-groups = 576 iterations (4 ulls each)
        for (int j = tid; j < 576; j += 192) {
            int c4 = j & 15, row = (j >> 4) % 6, ci = j / 96;
            int go = (ci * 64 + 2 * r + row) * 16 + c4;
            float4 a = s0[go], b = s0[go + 6144];
            ull* d = inP + ci * 384 + row * 64 + c4 * 4;
            d[0] = pk2(a.x, b.x); d[1] = pk2(a.y, b.y);
            d[2] = pk2(a.z, b.z); d[3] = pk2(a.w, b.w);
        }
    }
    __syncthreads();

    const int oc0 = warp * 3;
    ull acc[3][2][2];
#pragma unroll
    for (int oc = 0; oc < 3; oc++)
#pragma unroll
        for (int rr = 0; rr < 2; rr++) { acc[oc][rr][0] = 0ull; acc[oc][rr][1] = 0ull; }

#pragma unroll 1
    for (int ci = 0; ci < 6; ci++) {
        const ull* rb = inP + ci * 384 + 2 * lane;
#pragma unroll
        for (int iy = 0; iy < 6; iy++) {
            ull v[6];
            {
                v[0] = rb[iy * 64];
                v[1] = rb[iy * 64 + 1];
                v[2] = __shfl_down_sync(FULLM, v[0], 1);
                v[3] = __shfl_down_sync(FULLM, v[1], 1);
                v[4] = __shfl_down_sync(FULLM, v[0], 2);
                v[5] = __shfl_down_sync(FULLM, v[1], 2);
            }
#pragma unroll
            for (int rr = 0; rr < 2; rr++) {
                int ky = iy - rr;
                if (ky < 0 || ky > 4) continue;
#pragma unroll
                for (int oc = 0; oc < 3; oc++) {
                    const ull* w = g_wA + (oc0 + oc) * 150 + ci * 25 + ky * 5;
#pragma unroll
                    for (int kx = 0; kx < 5; kx++) {
                        ull wk = __ldg(w + kx);
                        ffma2(acc[oc][rr][0], wk, v[kx]);
                        ffma2(acc[oc][rr][1], wk, v[kx + 1]);
                    }
                }
            }
        }
    }
    if (lane < 30) {
#pragma unroll
        for (int oc = 0; oc < 3; oc++) {
            float b = __ldg(&g_b2[oc0 + oc]);
            float2 a0 = upk2(acc[oc][0][0]), a1 = upk2(acc[oc][0][1]);
            float2 b0 = upk2(acc[oc][1][0]), b1 = upk2(acc[oc][1][1]);
            float mx = fmaxf(fmaxf(a0.x, a1.x), fmaxf(b0.x, b1.x)) + b;
            float my = fmaxf(fmaxf(a0.y, a1.y), fmaxf(b0.y, b1.y)) + b;
            g_pool1p[(((size_t)pair * 18 + oc0 + oc) * 30 + r) * 30 + lane] = pk2(mx, my);
        }
    }
}

// ---------------- conv3: 18->18, 30x30 -> 28x28 ----------------
// grid (7 rowquads, 1024 pairs), 192 thr; lane = out col, halo via shfl.
__global__ __launch_bounds__(192, 6) void k_conv3(const float* __restrict__ c3b) {
    __shared__ __align__(16) ull pS[18 * 6 * 32 + 8];
    const int tid = threadIdx.x;
    const int lane = tid & 31, warp = tid >> 5;
    const int q = blockIdx.x;
    const int pair = blockIdx.y;

    {
        const ull* src = g_pool1p + (size_t)pair * 16200;
        for (int e = tid; e < 3240; e += 192) {
            int c = e % 30;
            int row = (e / 30) % 6;
            int ci = e / 180;
            pS[ci * 192 + row * 32 + c] = src[(ci * 30 + 4 * q + row) * 30 + c];
        }
    }
    __syncthreads();

    const int oc0 = warp * 3;
    ull acc[3][4];
#pragma unroll
    for (int oc = 0; oc < 3; oc++)
#pragma unroll
        for (int rr = 0; rr < 4; rr++) acc[oc][rr] = 0ull;

#pragma unroll 2
    for (int ci = 0; ci < 18; ci++) {
        const ull* rb = pS + ci * 192 + lane;
#pragma unroll
        for (int iy = 0; iy < 6; iy++) {
            ull v0 = rb[iy * 32];
            ull v1 = __shfl_down_sync(FULLM, v0, 1);
            ull v2 = __shfl_down_sync(FULLM, v0, 2);
#pragma unroll
            for (int rr = 0; rr < 4; rr++) {
                int ky = iy - rr;
                if (ky < 0 || ky > 2) continue;
#pragma unroll
                for (int oc = 0; oc < 3; oc++) {
                    const ull* w = g_w3 + (oc0 + oc) * 162 + ci * 9 + ky * 3;
                    ffma2(acc[oc][rr], __ldg(w), v0);
                    ffma2(acc[oc][rr], __ldg(w + 1), v1);
                    ffma2(acc[oc][rr], __ldg(w + 2), v2);
                }
            }
        }
    }
    if (lane < 28) {
#pragma unroll
        for (int oc = 0; oc < 3; oc++) {
            float b = __ldg(c3b + oc0 + oc);
            ull* zb = g_zp + (((size_t)pair * 18 + oc0 + oc) * 28 + 4 * q) * 28 + lane;
#pragma unroll
            for (int rr = 0; rr < 4; rr++) {
                float2 vv = upk2(acc[oc][rr]);
                zb[rr * 28] = pk2(vv.x + b, vv.y + b);
            }
        }
    }
}

// ---------------- conv4 body (NRO output rows) ----------------
template <int NRO>
__device__ __forceinline__ void conv4_body(const ull* zS, int lane, int oc0, ull (&acc)[3][4]) {
#pragma unroll 2
    for (int ci = 0; ci < 18; ci++) {
        const ull* rb = zS + ci * 168 + lane;
#pragma unroll
        for (int iy = 0; iy < NRO + 2; iy++) {
            ull v0 = rb[iy * 28];
            ull v1 = __shfl_down_sync(FULLM, v0, 1);
            ull v2 = __shfl_down_sync(FULLM, v0, 2);
#pragma unroll
            for (int rr = 0; rr < NRO; rr++) {
                int ky = iy - rr;
                if (ky < 0 || ky > 2) continue;
#pragma unroll
                for (int oc = 0; oc < 3; oc++) {
                    const ull* w = g_w4 + (oc0 + oc) * 162 + ci * 9 + ky * 3;
                    ffma2(acc[oc][rr], __ldg(w), v0);
                    ffma2(acc[oc][rr], __ldg(w + 1), v1);
                    ffma2(acc[oc][rr], __ldg(w + 2), v2);
                }
            }
        }
    }
}

// ---------------- conv4: 18->18, 28x28 -> 26x26 + avgpool -> 13x13 ----------------
// grid (7, 1024): x<6 -> 4 out rows (2 pooled), x=6 -> 2 out rows (1 pooled)
__global__ __launch_bounds__(192, 6) void k_conv4(const float* __restrict__ c4b) {
    __shared__ __align__(16) ull zS[18 * 6 * 28 + 8];
    const int tid = threadIdx.x;
    const int lane = tid & 31, warp = tid >> 5;
    const int x = blockIdx.x;
    const int pair = blockIdx.y;
    const int ir0 = 4 * x;
    const int n_in = (x < 6) ? 6 : 4;

    {
        const ull* src = g_zp + (size_t)pair * 14112;
        int per_ci = n_in * 28;
        int total = 18 * per_ci;
        for (int e = tid; e < total; e += 192) {
            int ci = e / per_ci, rem = e - ci * per_ci;
            int row = rem / 28, c = rem - row * 28;
            zS[ci * 168 + row * 28 + c] = src[(ci * 28 + ir0 + row) * 28 + c];
        }
    }
    __syncthreads();

    const int oc0 = warp * 3;
    ull acc[3][4];
#pragma unroll
    for (int oc = 0; oc < 3; oc++)
#pragma unroll
        for (int rr = 0; rr < 4; rr++) acc[oc][rr] = 0ull;

    int nro;
    if (x < 6) { conv4_body<4>(zS, lane, oc0, acc); nro = 4; }
    else       { conv4_body<2>(zS, lane, oc0, acc); nro = 2; }

#pragma unroll
    for (int oc = 0; oc < 3; oc++) {
        float b = __ldg(c4b + oc0 + oc);
#pragma unroll
        for (int pr = 0; pr < 2; pr++) {
            if (pr * 2 >= nro) break;
            float2 s0 = upk2(acc[oc][2 * pr]), s1 = upk2(acc[oc][2 * pr + 1]);
            float sx = s0.x + s1.x, sy = s0.y + s1.y;
            float ox = __shfl_down_sync(FULLM, sx, 1);
            float oy = __shfl_down_sync(FULLM, sy, 1);
            if (!(lane & 1) && lane < 26) {
                int prow = 2 * x + pr, pcol = lane >> 1;
                size_t fo = (size_t)(2 * pair) * 3042 + (oc0 + oc) * 169 + prow * 13 + pcol;
                g_feat[fo] = 0.25f * (sx + ox) + b;
                g_feat[fo + 3042] = 0.25f * (sy + oy) + b;
            }
        }
    }
}

// ---------------- MLP + expert routing + softmax, 8 samples/CTA ----------------
#define SMEM_M ((8 * 3076 + 64 * 132 + 8 * 66 + 512 + 64) * 4)

__global__ __launch_bounds__(512, 1) void k_mlp(const float* __restrict__ scores, const float* __restrict__ times,
                                                const int* __restrict__ agents,
                                                const float* __restrict__ l1w, const float* __restrict__ l1b,
                                                const float* __restrict__ l2w, const float* __restrict__ l2b,
                                                const float* __restrict__ agw, const float* __restrict__ agb,
                                                float* __restrict__ out) {
    extern __shared__ float smM[];
    float* featS = smM;                       // stride 3076 per sample
    float* wT = featS + 8 * 3076;             // 64 x 132
    float* h1S = wT + 64 * 132;               // stride 66
    float* h2S = h1S + 8 * 66;                // stride 64
    float* logS = h2S + 512;
    const int tid = threadIdx.x;
    const int sb = blockIdx.x * 8;

    for (int i = tid; i < 8 * 1521; i += 512) {
        int s = i / 1521;
        int r = i - s * 1521;
        ((float2*)(featS + s * 3076))[r] = ((const float2*)(g_feat + (size_t)(sb + s) * 3042))[r];
    }
    if (tid < 8) {
        featS[tid * 3076 + 3042] = scores[sb + tid];
        featS[tid * 3076 + 3043] = times[sb + tid];
    }
    if (tid >= 32 && tid < 288) {
        int j = tid - 32;                     // zero-pad k = 3044..3075
        featS[(j >> 5) * 3076 + 3044 + (j & 31)] = 0.f;
    }
    __syncthreads();

    const int s = tid & 7, o = tid >> 3;      // o 0..63; 8 lanes per o broadcast
    ull f0a = 0, f1a = 0, f2a = 0, f3a = 0;
#pragma unroll 1
    for (int kt = 0; kt < 24; kt++) {
        int k0 = kt << 7;
        for (int i = tid; i < 8192; i += 512) {
            int oo = i >> 7, kk = i & 127;
            int k = k0 + kk;
            wT[oo * 132 + kk] = (k < 3044) ? l1w[oo * 3044 + k] : 0.f;
        }
        __syncthreads();
        const ull* fr = (const ull*)(featS + s * 3076 + k0);
        const ull* wr = (const ull*)(wT + o * 132);
#pragma unroll
        for (int kk = 0; kk < 64; kk += 4) {
            ffma2(f0a, fr[kk], wr[kk]);
            ffma2(f1a, fr[kk + 1], wr[kk + 1]);
            ffma2(f2a, fr[kk + 2], wr[kk + 2]);
            ffma2(f3a, fr[kk + 3], wr[kk + 3]);
        }
        __syncthreads();
    }
    {
        float2 a = upk2(f0a), b = upk2(f1a), c = upk2(f2a), d = upk2(f3a);
        float acc = (a.x + a.y) + (b.x + b.y) + (c.x + c.y) + (d.x + d.y);
        h1S[s * 66 + o] = tanhf(acc + l1b[o]);
    }
    __syncthreads();
    {
        const ull* hr = (const ull*)(h1S + s * 66);
        const ull* w2 = (const ull*)(l2w + o * 64);
        ull a0 = 0, a1 = 0;
#pragma unroll
        for (int kk = 0; kk < 32; kk += 2) {
            ffma2(a0, hr[kk], w2[kk]);
            ffma2(a1, hr[kk + 1], w2[kk + 1]);
        }
        float2 a = upk2(a0), b = upk2(a1);
        h2S[s * 64 + o] = tanhf(a.x + a.y + b.x + b.y + l2b[o]);
    }
    __syncthreads();
    if (tid < 40) {
        int ss = tid / 5, oo = tid - ss * 5;
        int ag = agents[sb + ss];
        const float* W = agw + (ag * 5 + oo) * 64;
        const float* h = h2S + ss * 64;
        float a = agb[ag * 5 + oo];
#pragma unroll
        for (int k = 0; k < 64; k++) a += W[k] * h[k];
        logS[ss * 8 + oo] = a;
    }
    __syncthreads();
    if (tid < 8) {
        float m = -1e30f;
        for (int i = 0; i < 5; i++) m = fmaxf(m, logS[tid * 8 + i]);
        float e[5], sum = 0.f;
        for (int i = 0; i < 5; i++) { e[i] = expf(logS[tid * 8 + i] - m); sum += e[i]; }
        float inv = 1.f / sum;
        for (int i = 0; i < 5; i++) out[(sb + tid) * 5 + i] = e[i] * inv;
    }
}

// ---------------- launch ----------------
extern "C" void kernel_launch(void* const* d_in, const int* in_sizes, int n_in,
                              void* d_out, int out_size) {
    const float* states = (const float*)d_in[0];
    const float* scores = (const float*)d_in[1];
    const float* times  = (const float*)d_in[2];
    const int*   agents = (const int*)d_in[3];
    const float* c1w = (const float*)d_in[4];
    const float* c1b = (const float*)d_in[5];
    const float* c2w = (const float*)d_in[6];
    const float* c2b = (const float*)d_in[7];
    const float* c3w = (const float*)d_in[8];
    const float* c3b = (const float*)d_in[9];
    const float* c4w = (const float*)d_in[10];
    const float* c4b = (const float*)d_in[11];
    const float* l1w = (const float*)d_in[12];
    const float* l1b = (const float*)d_in[13];
    const float* l2w = (const float*)d_in[14];
    const float* l2b = (const float*)d_in[15];
    const float* agw = (const float*)d_in[16];
    const float* agb = (const float*)d_in[17];
    float* out = (float*)d_out;

    cudaFuncSetAttribute(k_mlp, cudaFuncAttributeMaxDynamicSharedMemorySize, SMEM_M);

    k_compose<<<3, 1024>>>(c1w, c1b, c2w, c2b);
    k_packw<<<6, 512>>>(c3w, c4w);
    k_convA<<<dim3(30, 1024), 192>>>(states);
    k_conv3<<<dim3(7, 1024), 192>>>(c3b);
    k_conv4<<<dim3(7, 1024), 192>>>(c4b);
    k_mlp<<<256, 512, SMEM_M>>>(scores, times, agents, l1w, l1b, l2w, l2b, agw, agb, out);
}

// round 8
// speedup vs baseline: 2.1114x; 2.1114x over previous
#include <cuda_runtime.h>
#include <math.h>

typedef unsigned long long ull;

#define NBATCH 2048
#define NPAIR 1024
#define FULLM 0xffffffffu

// ---------------- device scratch ----------------
__device__ __align__(16) ull g_wA[2700];                             // composed 5x5 weights (w,w) pairs
__device__ float g_b2[18];                                           // composed bias
__device__ __align__(16) ull g_w3[2916];                             // c3 weights (w,w)
__device__ __align__(16) ull g_w4[2916];                             // c4 weights (w,w)
__device__ __align__(16) ull g_pool1p[(size_t)NPAIR * 18 * 30 * 30]; // pool1, sample-pair interleaved
__device__ __align__(16) ull g_zp[(size_t)NPAIR * 18 * 28 * 28];     // conv3 out, interleaved
__device__ __align__(16) float g_feat[(size_t)NBATCH * 3042];        // flattened features

// ---------------- packed f32x2 helpers ----------------
__device__ __forceinline__ void ffma2(ull& d, ull a, ull b) {
    asm("fma.rn.f32x2 %0, %1, %2, %0;" : "+l"(d) : "l"(a), "l"(b));
}
__device__ __forceinline__ ull pk2(float lo, float hi) {
    ull r;
    asm("mov.b64 %0, {%1, %2};" : "=l"(r) : "f"(lo), "f"(hi));
    return r;
}
__device__ __forceinline__ float2 upk2(ull v) {
    float2 r;
    asm("mov.b64 {%0, %1}, %2;" : "=f"(r.x), "=f"(r.y) : "l"(v));
    return r;
}

// ---------------- compose conv1*conv2 -> one 5x5 conv ----------------
__global__ void k_compose(const float* __restrict__ c1w, const float* __restrict__ c1b,
                          const float* __restrict__ c2w, const float* __restrict__ c2b) {
    int idx = blockIdx.x * blockDim.x + threadIdx.x;
    if (idx < 2700) {
        int o = idx / 150;
        int ci = (idx / 25) % 6;
        int y = (idx % 25) / 5;
        int x = idx % 5;
        int ky_lo = y > 2 ? y - 2 : 0, ky_hi = y < 2 ? y : 2;
        int kx_lo = x > 2 ? x - 2 : 0, kx_hi = x < 2 ? x : 2;
        float s = 0.f;
        for (int m = 0; m < 18; m++)
            for (int ky = ky_lo; ky <= ky_hi; ky++)
                for (int kx = kx_lo; kx <= kx_hi; kx++)
                    s += c1w[((m * 6 + ci) * 3 + ky) * 3 + kx] *
                         c2w[((o * 18 + m) * 3 + (y - ky)) * 3 + (x - kx)];
        g_wA[idx] = pk2(s, s);
    } else if (idx < 2718) {
        int o = idx - 2700;
        float s = c2b[o];
        for (int m = 0; m < 18; m++) {
            float t = 0.f;
            for (int q = 0; q < 9; q++) t += c2w[(o * 18 + m) * 9 + q];
            s += c1b[m] * t;
        }
        g_b2[o] = s;
    }
}

__global__ void k_packw(const float* __restrict__ c3w, const float* __restrict__ c4w) {
    int idx = blockIdx.x * blockDim.x + threadIdx.x;
    if (idx < 2916) {
        float a = c3w[idx], b = c4w[idx];
        g_w3[idx] = pk2(a, a);
        g_w4[idx] = pk2(b, b);
    }
}

// ---------------- convA: composed 5x5 (6->18) + maxpool2  (R4 version, measured-good) ----------------
// grid (5 rowbands, 1024 pairs), 512 thr, 2 CTAs/SM
// smem: W2ps 21600 | b2s 96 | inP 6*16*64 ull = 49152  => 70848
#define SMEM_A 70848

__global__ __launch_bounds__(512, 2) void k_convA(const float* __restrict__ states) {
    extern __shared__ char smA[];
    ull* W2ps = (ull*)smA;
    float* b2s = (float*)(smA + 21600);
    ull* inP = (ull*)(smA + 21696);
    const int tid = threadIdx.x;
    const int band = blockIdx.x;       // 0..4, 6 pooled rows each
    const int pair = blockIdx.y;
    const int ir0 = 12 * band;         // first input row of this band (16 rows used)

    for (int i = tid; i < 2700; i += 512) W2ps[i] = g_wA[i];
    if (tid < 18) b2s[tid] = g_b2[tid];
    {
        const float4* s0 = (const float4*)(states) + (size_t)pair * 12288;
        for (int i = tid; i < 1536; i += 512) {
            int c4 = i & 15, r = (i >> 4) & 15, ci = i >> 8;
            int goff = (ci * 64 + ir0 + r) * 16 + c4;
            float4 a = s0[goff], b = s0[goff + 6144];
            ull* d = inP + (ci << 10) + (r << 6) + (c4 << 2);
            d[0] = pk2(a.x, b.x); d[1] = pk2(a.y, b.y);
            d[2] = pk2(a.z, b.z); d[3] = pk2(a.w, b.w);
        }
    }
    __syncthreads();

    // strips: pl(6) x blk(10) x oc(18) = 1080; oc fastest (warp-broadcast data LDS)
    for (int t = tid; t < 1080; t += 512) {
        int oc = t % 18;
        int r2 = t / 18;
        int blk = r2 % 10;
        int pl = r2 / 10;          // local pooled row 0..5
        int c0 = blk * 6;

        ull acc[2][6];
#pragma unroll
        for (int r = 0; r < 2; r++)
#pragma unroll
            for (int j = 0; j < 6; j++) acc[r][j] = 0ull;

#pragma unroll 1
        for (int ci = 0; ci < 6; ci++) {
            const ull* rb = inP + (ci << 10) + (pl << 7) + c0;   // 2*pl*64 = pl<<7
            const ull* wc = W2ps + oc * 150 + ci * 25;
#pragma unroll
            for (int iy = 0; iy < 6; iy++) {
                ull v[10];
                {
                    const ull* vp = rb + (iy << 6);
#pragma unroll
                    for (int j = 0; j < 10; j++) v[j] = vp[j];
                }
                if (iy < 5) {
#pragma unroll
                    for (int kx = 0; kx < 5; kx++) {
                        ull w = wc[iy * 5 + kx];
#pragma unroll
                        for (int j = 0; j < 6; j++) ffma2(acc[0][j], w, v[j + kx]);
                    }
                }
                if (iy >= 1) {
#pragma unroll
                    for (int kx = 0; kx < 5; kx++) {
                        ull w = wc[(iy - 1) * 5 + kx];
#pragma unroll
                        for (int j = 0; j < 6; j++) ffma2(acc[1][j], w, v[j + kx]);
                    }
                }
            }
        }
        float bias = b2s[oc];
        int prow = band * 6 + pl;
        ull* op = g_pool1p + (((size_t)pair * 18 + oc) * 30 + prow) * 30 + blk * 3;
#pragma unroll
        for (int p = 0; p < 3; p++) {
            float2 a0 = upk2(acc[0][2 * p]), a1 = upk2(acc[0][2 * p + 1]);
            float2 b0 = upk2(acc[1][2 * p]), b1 = upk2(acc[1][2 * p + 1]);
            float2 m;
            m.x = fmaxf(fmaxf(a0.x, a1.x), fmaxf(b0.x, b1.x)) + bias;
            m.y = fmaxf(fmaxf(a0.y, a1.y), fmaxf(b0.y, b1.y)) + bias;
            ((float2*)op)[p] = m;
        }
    }
}

// ---------------- conv3: 18->18, 30x30 -> 28x28 ----------------
// grid (7 rowquads, 1024 pairs), 192 thr, 3 CTAs/SM; lane = out col, halo via shfl.
// weights: smem -> per-ci distinct-lane LDS + shfl broadcast into 27 registers.
// dyn smem: w3s 23328 | pS 27648 | b3s 96 => 51072
#define SMEM_C3 51072

__global__ __launch_bounds__(192, 3) void k_conv3(const float* __restrict__ c3b) {
    extern __shared__ char smC[];
    ull* w3s = (ull*)smC;
    ull* pS = (ull*)(smC + 23328);
    float* b3s = (float*)(smC + 23328 + 27648);
    const int tid = threadIdx.x;
    const int lane = tid & 31, warp = tid >> 5;
    const int q = blockIdx.x;
    const int pair = blockIdx.y;

    for (int i = tid; i < 2916; i += 192) w3s[i] = g_w3[i];
    if (tid < 18) b3s[tid] = c3b[tid];
    {
        const ull* src = g_pool1p + (size_t)pair * 16200;
        for (int e = tid; e < 3240; e += 192) {
            int c = e % 30;
            int row = (e / 30) % 6;
            int ci = e / 180;
            pS[ci * 192 + row * 32 + c] = src[(ci * 30 + 4 * q + row) * 30 + c];
        }
    }
    __syncthreads();

    const int oc0 = warp * 3;
    // per-lane weight gather address (lane -> oc=lane/9, k=lane%9)
    const int wl = (lane < 27) ? ((oc0 + lane / 9) * 162 + (lane % 9)) : 0;

    ull acc[3][4];
#pragma unroll
    for (int oc = 0; oc < 3; oc++)
#pragma unroll
        for (int rr = 0; rr < 4; rr++) acc[oc][rr] = 0ull;

#pragma unroll 1
    for (int ci = 0; ci < 18; ci++) {
        ull wld = w3s[wl + ci * 9];   // distinct-lane fetch (lanes 0..26)
        ull w[27];
#pragma unroll
        for (int k = 0; k < 27; k++) w[k] = __shfl_sync(FULLM, wld, k);

        const ull* rb = pS + ci * 192 + lane;
#pragma unroll
        for (int iy = 0; iy < 6; iy++) {
            ull v0 = rb[iy * 32];
            ull v1 = __shfl_down_sync(FULLM, v0, 1);
            ull v2 = __shfl_down_sync(FULLM, v0, 2);
#pragma unroll
            for (int rr = 0; rr < 4; rr++) {
                int ky = iy - rr;
                if (ky < 0 || ky > 2) continue;
#pragma unroll
                for (int oc = 0; oc < 3; oc++) {
                    ffma2(acc[oc][rr], w[oc * 9 + ky * 3], v0);
                    ffma2(acc[oc][rr], w[oc * 9 + ky * 3 + 1], v1);
                    ffma2(acc[oc][rr], w[oc * 9 + ky * 3 + 2], v2);
                }
            }
        }
    }
    if (lane < 28) {
#pragma unroll
        for (int oc = 0; oc < 3; oc++) {
            float b = b3s[oc0 + oc];
            ull* zb = g_zp + (((size_t)pair * 18 + oc0 + oc) * 28 + 4 * q) * 28 + lane;
#pragma unroll
            for (int rr = 0; rr < 4; rr++) {
                float2 vv = upk2(acc[oc][rr]);
                zb[rr * 28] = pk2(vv.x + b, vv.y + b);
            }
        }
    }
}

// ---------------- conv4 body (NRO output rows) ----------------
template <int NRO>
__device__ __forceinline__ void conv4_body(const ull* zS, const ull* w4s, int lane, int wl,
                                           ull (&acc)[3][4]) {
#pragma unroll 1
    for (int ci = 0; ci < 18; ci++) {
        ull wld = w4s[wl + ci * 9];
        ull w[27];
#pragma unroll
        for (int k = 0; k < 27; k++) w[k] = __shfl_sync(FULLM, wld, k);

        const ull* rb = zS + ci * 168 + lane;
#pragma unroll
        for (int iy = 0; iy < NRO + 2; iy++) {
            ull v0 = rb[iy * 28];
            ull v1 = __shfl_down_sync(FULLM, v0, 1);
            ull v2 = __shfl_down_sync(FULLM, v0, 2);
#pragma unroll
            for (int rr = 0; rr < NRO; rr++) {
                int ky = iy - rr;
                if (ky < 0 || ky > 2) continue;
#pragma unroll
                for (int oc = 0; oc < 3; oc++) {
                    ffma2(acc[oc][rr], w[oc * 9 + ky * 3], v0);
                    ffma2(acc[oc][rr], w[oc * 9 + ky * 3 + 1], v1);
                    ffma2(acc[oc][rr], w[oc * 9 + ky * 3 + 2], v2);
                }
            }
        }
    }
}

// ---------------- conv4: 18->18, 28x28 -> 26x26 + avgpool -> 13x13 ----------------
// grid (7, 1024): x<6 -> 4 out rows (2 pooled), x=6 -> 2 out rows (1 pooled)
// dyn smem: w4s 23328 | zS 24192 | b4s 96 => 47616
#define SMEM_C4 47616

__global__ __launch_bounds__(192, 3) void k_conv4(const float* __restrict__ c4b) {
    extern __shared__ char smD[];
    ull* w4s = (ull*)smD;
    ull* zS = (ull*)(smD + 23328);
    float* b4s = (float*)(smD + 23328 + 24192);
    const int tid = threadIdx.x;
    const int lane = tid & 31, warp = tid >> 5;
    const int x = blockIdx.x;
    const int pair = blockIdx.y;
    const int ir0 = 4 * x;
    const int n_in = (x < 6) ? 6 : 4;

    for (int i = tid; i < 2916; i += 192) w4s[i] = g_w4[i];
    if (tid < 18) b4s[tid] = c4b[tid];
    {
        const ull* src = g_zp + (size_t)pair * 14112;
        int per_ci = n_in * 28;
        int total = 18 * per_ci;
        for (int e = tid; e < total; e += 192) {
            int ci = e / per_ci, rem = e - ci * per_ci;
            int row = rem / 28, c = rem - row * 28;
            zS[ci * 168 + row * 28 + c] = src[(ci * 28 + ir0 + row) * 28 + c];
        }
    }
    __syncthreads();

    const int oc0 = warp * 3;
    const int wl = (lane < 27) ? ((oc0 + lane / 9) * 162 + (lane % 9)) : 0;

    ull acc[3][4];
#pragma unroll
    for (int oc = 0; oc < 3; oc++)
#pragma unroll
        for (int rr = 0; rr < 4; rr++) acc[oc][rr] = 0ull;

    int nro;
    if (x < 6) { conv4_body<4>(zS, w4s, lane, wl, acc); nro = 4; }
    else       { conv4_body<2>(zS, w4s, lane, wl, acc); nro = 2; }

#pragma unroll
    for (int oc = 0; oc < 3; oc++) {
        float b = b4s[oc0 + oc];
#pragma unroll
        for (int pr = 0; pr < 2; pr++) {
            if (pr * 2 >= nro) break;
            float2 s0 = upk2(acc[oc][2 * pr]), s1 = upk2(acc[oc][2 * pr + 1]);
            float sx = s0.x + s1.x, sy = s0.y + s1.y;
            float ox = __shfl_down_sync(FULLM, sx, 1);
            float oy = __shfl_down_sync(FULLM, sy, 1);
            if (!(lane & 1) && lane < 26) {
                int prow = 2 * x + pr, pcol = lane >> 1;
                size_t fo = (size_t)(2 * pair) * 3042 + (oc0 + oc) * 169 + prow * 13 + pcol;
                g_feat[fo] = 0.25f * (sx + ox) + b;
                g_feat[fo + 3042] = 0.25f * (sy + oy) + b;
            }
        }
    }
}

// ---------------- MLP + expert routing + softmax, 8 samples/CTA ----------------
#define SMEM_M ((8 * 3076 + 64 * 132 + 8 * 66 + 512 + 64) * 4)

__global__ __launch_bounds__(512, 1) void k_mlp(const float* __restrict__ scores, const float* __restrict__ times,
                                                const int* __restrict__ agents,
                                                const float* __restrict__ l1w, const float* __restrict__ l1b,
                                                const float* __restrict__ l2w, const float* __restrict__ l2b,
                                                const float* __restrict__ agw, const float* __restrict__ agb,
                                                float* __restrict__ out) {
    extern __shared__ float smM[];
    float* featS = smM;                       // stride 3076 per sample
    float* wT = featS + 8 * 3076;             // 64 x 132
    float* h1S = wT + 64 * 132;               // stride 66
    float* h2S = h1S + 8 * 66;                // stride 64
    float* logS = h2S + 512;
    const int tid = threadIdx.x;
    const int sb = blockIdx.x * 8;

    for (int i = tid; i < 8 * 1521; i += 512) {
        int s = i / 1521;
        int r = i - s * 1521;
        ((float2*)(featS + s * 3076))[r] = ((const float2*)(g_feat + (size_t)(sb + s) * 3042))[r];
    }
    if (tid < 8) {
        featS[tid * 3076 + 3042] = scores[sb + tid];
        featS[tid * 3076 + 3043] = times[sb + tid];
    }
    if (tid >= 32 && tid < 288) {
        int j = tid - 32;                     // zero-pad k = 3044..3075
        featS[(j >> 5) * 3076 + 3044 + (j & 31)] = 0.f;
    }
    __syncthreads();

    const int s = tid & 7, o = tid >> 3;      // o 0..63; 8 lanes per o broadcast
    ull f0a = 0, f1a = 0, f2a = 0, f3a = 0;
#pragma unroll 1
    for (int kt = 0; kt < 24; kt++) {
        int k0 = kt << 7;
        for (int i = tid; i < 8192; i += 512) {
            int oo = i >> 7, kk = i & 127;
            int k = k0 + kk;
            wT[oo * 132 + kk] = (k < 3044) ? l1w[oo * 3044 + k] : 0.f;
        }
        __syncthreads();
        const ull* fr = (const ull*)(featS + s * 3076 + k0);
        const ull* wr = (const ull*)(wT + o * 132);
#pragma unroll
        for (int kk = 0; kk < 64; kk += 4) {
            ffma2(f0a, fr[kk], wr[kk]);
            ffma2(f1a, fr[kk + 1], wr[kk + 1]);
            ffma2(f2a, fr[kk + 2], wr[kk + 2]);
            ffma2(f3a, fr[kk + 3], wr[kk + 3]);
        }
        __syncthreads();
    }
    {
        float2 a = upk2(f0a), b = upk2(f1a), c = upk2(f2a), d = upk2(f3a);
        float acc = (a.x + a.y) + (b.x + b.y) + (c.x + c.y) + (d.x + d.y);
        h1S[s * 66 + o] = tanhf(acc + l1b[o]);
    }
    __syncthreads();
    {
        const ull* hr = (const ull*)(h1S + s * 66);
        const ull* w2 = (const ull*)(l2w + o * 64);
        ull a0 = 0, a1 = 0;
#pragma unroll
        for (int kk = 0; kk < 32; kk += 2) {
            ffma2(a0, hr[kk], w2[kk]);
            ffma2(a1, hr[kk + 1], w2[kk + 1]);
        }
        float2 a = upk2(a0), b = upk2(a1);
        h2S[s * 64 + o] = tanhf(a.x + a.y + b.x + b.y + l2b[o]);
    }
    __syncthreads();
    if (tid < 40) {
        int ss = tid / 5, oo = tid - ss * 5;
        int ag = agents[sb + ss];
        const float* W = agw + (ag * 5 + oo) * 64;
        const float* h = h2S + ss * 64;
        float a = agb[ag * 5 + oo];
#pragma unroll
        for (int k = 0; k < 64; k++) a += W[k] * h[k];
        logS[ss * 8 + oo] = a;
    }
    __syncthreads();
    if (tid < 8) {
        float m = -1e30f;
        for (int i = 0; i < 5; i++) m = fmaxf(m, logS[tid * 8 + i]);
        float e[5], sum = 0.f;
        for (int i = 0; i < 5; i++) { e[i] = expf(logS[tid * 8 + i] - m); sum += e[i]; }
        float inv = 1.f / sum;
        for (int i = 0; i < 5; i++) out[(sb + tid) * 5 + i] = e[i] * inv;
    }
}

// ---------------- launch ----------------
extern "C" void kernel_launch(void* const* d_in, const int* in_sizes, int n_in,
                              void* d_out, int out_size) {
    const float* states = (const float*)d_in[0];
    const float* scores = (const float*)d_in[1];
    const float* times  = (const float*)d_in[2];
    const int*   agents = (const int*)d_in[3];
    const float* c1w = (const float*)d_in[4];
    const float* c1b = (const float*)d_in[5];
    const float* c2w = (const float*)d_in[6];
    const float* c2b = (const float*)d_in[7];
    const float* c3w = (const float*)d_in[8];
    const float* c3b = (const float*)d_in[9];
    const float* c4w = (const float*)d_in[10];
    const float* c4b = (const float*)d_in[11];
    const float* l1w = (const float*)d_in[12];
    const float* l1b = (const float*)d_in[13];
    const float* l2w = (const float*)d_in[14];
    const float* l2b = (const float*)d_in[15];
    const float* agw = (const float*)d_in[16];
    const float* agb = (const float*)d_in[17];
    float* out = (float*)d_out;

    cudaFuncSetAttribute(k_convA, cudaFuncAttributeMaxDynamicSharedMemorySize, SMEM_A);
    cudaFuncSetAttribute(k_conv3, cudaFuncAttributeMaxDynamicSharedMemorySize, SMEM_C3);
    cudaFuncSetAttribute(k_conv4, cudaFuncAttributeMaxDynamicSharedMemorySize, SMEM_C4);
    cudaFuncSetAttribute(k_mlp, cudaFuncAttributeMaxDynamicSharedMemorySize, SMEM_M);

    k_compose<<<3, 1024>>>(c1w, c1b, c2w, c2b);
    k_packw<<<6, 512>>>(c3w, c4w);
    k_convA<<<dim3(5, 1024), 512, SMEM_A>>>(states);
    k_conv3<<<dim3(7, 1024), 192, SMEM_C3>>>(c3b);
    k_conv4<<<dim3(7, 1024), 192, SMEM_C4>>>(c4b);
    k_mlp<<<256, 512, SMEM_M>>>(scores, times, agents, l1w, l1b, l2w, l2b, agw, agb, out);
}